// round 3
// baseline (speedup 1.0000x reference)
#include <cuda_runtime.h>
#include <cstdint>

// SigJoin (Chen's identity), D=8, M=6, BATCH=128.
// z_k[j] = x_k[j] + sum_{i=0}^{k-1} X_i * prod_{t=i}^{k-1} y[d_t] / (k-i)!
// with X_0 = 1, X_i = x_i[j >> 3*(k-i)], d_t = base-8 digits of j.
// All cross terms share the last-digit factor y[d_{k-1}]; 4-aligned indices
// share all prefix digits -> one scalar A per float4, z = x + A*y[last 4 digits].

#define SJ_D      8
#define SJ_M      6
#define SJ_SIGLEN 299592
#define SJ_BATCH  128

__device__ __forceinline__ float sj_invf(int n) {
    // 1/n! for n=1..6
    const float t[7] = {0.f, 1.f, 0.5f, 1.f/6.f, 1.f/24.f, 1.f/120.f, 1.f/720.f};
    return t[n];
}

// Per-level offsets within a row (level i data starts at loff[i], i=1..6)
__device__ __forceinline__ int sj_loff(int i) {
    const int t[7] = {0, 0, 8, 72, 584, 4680, 37448};
    return t[i];
}

// Compute A = sum_{i=0}^{K-1} X_i * P_i * invf(K-i), P_i = prod_{t=i}^{K-2} y[d_t].
// (Suffix products EXCLUDING the last digit; caller multiplies by y[d_{K-1}].)
template <int K>
__device__ __forceinline__ float sj_chenA(const float* __restrict__ xr,
                                          const float* __restrict__ ys,
                                          int r) {
    float A = 0.f;
    float P = 1.f;
    int idx = r;
#pragma unroll
    for (int i = K - 1; i >= 1; --i) {
        idx >>= 3;                       // idx = r >> 3*(K-i)
        A += __ldg(xr + sj_loff(i) + idx) * (P * sj_invf(K - i));
        P *= ys[idx & 7];                // fold in digit d_{i-1}
    }
    A += P * sj_invf(K);                 // i = 0 term (pure exp term), X_0 = 1
    return A;
}

__global__ __launch_bounds__(256) void sigjoin_kernel(
    const float* __restrict__ x,   // [BATCH, SIGLEN]
    const float* __restrict__ y,   // [BATCH, 8]
    float* __restrict__ out)       // [BATCH, SIGLEN]
{
    const int b = blockIdx.y;
    __shared__ float ys[8];
    if (threadIdx.x < 8) ys[threadIdx.x] = y[b * SJ_D + threadIdx.x];
    __syncthreads();

    const int c4 = blockIdx.x * blockDim.x + threadIdx.x;
    const int c  = c4 * 4;                 // column of first element (4-aligned)
    if (c >= SJ_SIGLEN) return;

    const float* xr   = x   + (size_t)b * SJ_SIGLEN;
    float*       orow = out + (size_t)b * SJ_SIGLEN;

    const float4 xv = *reinterpret_cast<const float4*>(xr + c);

    // Determine level and compute the shared prefix accumulator A.
    float A;
    int r;
    if (c >= 37448)      { r = c - 37448; A = sj_chenA<6>(xr, ys, r); }
    else if (c >= 4680)  { r = c - 4680;  A = sj_chenA<5>(xr, ys, r); }
    else if (c >= 584)   { r = c - 584;   A = sj_chenA<4>(xr, ys, r); }
    else if (c >= 72)    { r = c - 72;    A = sj_chenA<3>(xr, ys, r); }
    else if (c >= 8)     { r = c - 8;     A = sj_chenA<2>(xr, ys, r); }
    else                 { r = c;         A = sj_chenA<1>(xr, ys, r); }

    // Last digit of the 4 elements: (r&7), (r&7)+1, ... (no carry: r%4==0 -> r&7 in {0,4})
    const int d = r & 7;
    float4 zv;
    zv.x = fmaf(A, ys[d + 0], xv.x);
    zv.y = fmaf(A, ys[d + 1], xv.y);
    zv.z = fmaf(A, ys[d + 2], xv.z);
    zv.w = fmaf(A, ys[d + 3], xv.w);

    *reinterpret_cast<float4*>(orow + c) = zv;
}

extern "C" void kernel_launch(void* const* d_in, const int* in_sizes, int n_in,
                              void* d_out, int out_size) {
    const float* x = (const float*)d_in[0];   // [128, 299592] fp32
    const float* y = (const float*)d_in[1];   // [128, 8] fp32
    float* out = (float*)d_out;

    const int n4 = SJ_SIGLEN / 4;             // 74898 float4s per row
    dim3 block(256);
    dim3 grid((n4 + 255) / 256, SJ_BATCH);
    sigjoin_kernel<<<grid, block>>>(x, y, out);
}

// round 4
// speedup vs baseline: 1.3641x; 1.3641x over previous
#include <cuda_runtime.h>
#include <cstdint>

// SigJoin (Chen's identity), D=8, M=6, BATCH=128, SIGLEN=299592.
// z_k[j] = x_k[j] + A(j>>3) * y[j&7], where
// A = sum_{i=0}^{k-1} X_i * (prod_{t=i}^{k-2} y[d_t]) / (k-i)!,  X_0=1, X_i=x_i[j>>3(k-i)].
// A is constant over each aligned 8-element group -> one thread per group,
// 8 floats (2x float4) per thread.

#define SJ_D      8
#define SJ_SIGLEN 299592
#define SJ_BATCH  128
#define SJ_GROUPS (SJ_SIGLEN / 8)   // 37449 groups per row

__device__ __forceinline__ float sj_invf(int n) {
    const float t[7] = {0.f, 1.f, 0.5f, 1.f/6.f, 1.f/24.f, 1.f/120.f, 1.f/720.f};
    return t[n];
}

__device__ __forceinline__ int sj_loff(int i) {
    const int t[7] = {0, 0, 8, 72, 584, 4680, 37448};
    return t[i];
}

// A = sum_{i=0}^{K-1} X_i * P_i * invf(K-i),  P_i = prod_{t=i}^{K-2} y[d_t].
// r = group-local offset (multiple of 8): first >>3 yields the group prefix p.
template <int K>
__device__ __forceinline__ float sj_chenA(const float* __restrict__ xr,
                                          const float* __restrict__ ys,
                                          int r) {
    float A = 0.f;
    float P = 1.f;
    int idx = r;
#pragma unroll
    for (int i = K - 1; i >= 1; --i) {
        idx >>= 3;                                   // idx = r >> 3*(K-i)
        A += __ldg(xr + sj_loff(i) + idx) * (P * sj_invf(K - i));
        P *= ys[idx & 7];                            // fold digit d_{i-1}
    }
    return A + P * sj_invf(K);                       // i=0 term (pure exp), X_0=1
}

__global__ __launch_bounds__(256) void sigjoin8_kernel(
    const float* __restrict__ x,   // [BATCH, SIGLEN]
    const float* __restrict__ y,   // [BATCH, 8]
    float* __restrict__ out)       // [BATCH, SIGLEN]
{
    const int b = blockIdx.y;
    __shared__ float ys[8];
    if (threadIdx.x < 8) ys[threadIdx.x] = y[b * SJ_D + threadIdx.x];
    __syncthreads();

    const int g = blockIdx.x * blockDim.x + threadIdx.x;  // group index
    if (g >= SJ_GROUPS) return;
    const int c = g * 8;                                  // first column of group

    const float* xr   = x   + (size_t)b * SJ_SIGLEN;
    float*       orow = out + (size_t)b * SJ_SIGLEN;

    // Streaming bulk loads (no reuse of the level-k body beyond prefix levels).
    const float4 x0 = __ldcs(reinterpret_cast<const float4*>(xr + c));
    const float4 x1 = __ldcs(reinterpret_cast<const float4*>(xr + c + 4));

    // Level dispatch + shared prefix accumulator A (one per 8-group).
    float A;
    if (c >= 37448)      A = sj_chenA<6>(xr, ys, c - 37448);
    else if (c >= 4680)  A = sj_chenA<5>(xr, ys, c - 4680);
    else if (c >= 584)   A = sj_chenA<4>(xr, ys, c - 584);
    else if (c >= 72)    A = sj_chenA<3>(xr, ys, c - 72);
    else if (c >= 8)     A = sj_chenA<2>(xr, ys, c - 8);
    else                 A = 1.f;                         // level 1: z = x + y

    float4 z0, z1;
    z0.x = fmaf(A, ys[0], x0.x);
    z0.y = fmaf(A, ys[1], x0.y);
    z0.z = fmaf(A, ys[2], x0.z);
    z0.w = fmaf(A, ys[3], x0.w);
    z1.x = fmaf(A, ys[4], x1.x);
    z1.y = fmaf(A, ys[5], x1.y);
    z1.z = fmaf(A, ys[6], x1.z);
    z1.w = fmaf(A, ys[7], x1.w);

    __stcs(reinterpret_cast<float4*>(orow + c),     z0);
    __stcs(reinterpret_cast<float4*>(orow + c + 4), z1);
}

extern "C" void kernel_launch(void* const* d_in, const int* in_sizes, int n_in,
                              void* d_out, int out_size) {
    const float* x = (const float*)d_in[0];   // [128, 299592] fp32
    const float* y = (const float*)d_in[1];   // [128, 8] fp32
    float* out = (float*)d_out;

    dim3 block(256);
    dim3 grid((SJ_GROUPS + 255) / 256, SJ_BATCH);   // 147 x 128
    sigjoin8_kernel<<<grid, block>>>(x, y, out);
}